// round 1
// baseline (speedup 1.0000x reference)
#include <cuda_runtime.h>
#include <math_constants.h>

// Problem constants
#define B_  64
#define T_  1380
#define XD  96
#define HD  192
#define CN  345

static __device__ __constant__ float kScale = 0.0073656956f; // 1/sqrt(96*192)

// Scratch (device globals; no allocation allowed in kernel_launch)
__device__ float g_Z[(size_t)B_ * CN * XD];   // 8.5 MB   Z = W2 @ X
__device__ float g_Y[(size_t)B_ * CN * HD];   // 17 MB    Y = Z @ W1
__device__ float g_L[(size_t)B_ * CN * T_];   // 122 MB   logits / probs

// ---------------------------------------------------------------------------
// Tiled NN GEMM: C[b] = alpha * A[b](MxK, row-major) @ B[b](KxN, row-major)
// 64x64 tile, 256 threads, 4x4 per-thread microtile, BK=16.
// ---------------------------------------------------------------------------
template<int M, int N, int K>
__global__ void gemm_nn(const float* __restrict__ A, size_t sA,
                        const float* __restrict__ Bm, size_t sB,
                        float* __restrict__ Cm, size_t sC, float alpha) {
    const int b = blockIdx.z;
    A  += sA * b;
    Bm += sB * b;
    Cm += sC * b;
    const int m0 = blockIdx.x * 64;
    const int n0 = blockIdx.y * 64;

    __shared__ __align__(16) float As[16][68];  // [k][m], padded: 2-way max on store
    __shared__ __align__(16) float Bs[16][64];  // [k][n], natural layout

    const int tid = threadIdx.x;
    const int ty = tid >> 4;      // 0..15 -> 4 rows each
    const int tx = tid & 15;      // 0..15 -> 4 cols each

    float acc[4][4] = {};

    for (int k0 = 0; k0 < K; k0 += 16) {
        // Load A tile (transposed store into As[k][m])
        #pragma unroll
        for (int i = 0; i < 4; i++) {
            int idx = tid + i * 256;          // 1024 elems
            int r = idx >> 4, k = idx & 15;   // consecutive tid -> consecutive k (coalesced 64B)
            int gm = m0 + r, gk = k0 + k;
            As[k][r] = (gm < M && gk < K) ? A[(size_t)gm * K + gk] : 0.f;
        }
        // Load B tile (natural store, fully coalesced)
        #pragma unroll
        for (int i = 0; i < 4; i++) {
            int idx = tid + i * 256;
            int k = idx >> 6, n = idx & 63;
            int gk = k0 + k, gn = n0 + n;
            Bs[k][n] = (gk < K && gn < N) ? Bm[(size_t)gk * N + gn] : 0.f;
        }
        __syncthreads();

        #pragma unroll
        for (int kk = 0; kk < 16; kk++) {
            float4 av = *reinterpret_cast<const float4*>(&As[kk][ty * 4]);
            float4 bv = *reinterpret_cast<const float4*>(&Bs[kk][tx * 4]);
            float a[4] = {av.x, av.y, av.z, av.w};
            float bb[4] = {bv.x, bv.y, bv.z, bv.w};
            #pragma unroll
            for (int r = 0; r < 4; r++)
                #pragma unroll
                for (int c = 0; c < 4; c++)
                    acc[r][c] += a[r] * bb[c];
        }
        __syncthreads();
    }

    #pragma unroll
    for (int r = 0; r < 4; r++) {
        int gm = m0 + ty * 4 + r;
        if (gm < M) {
            #pragma unroll
            for (int c = 0; c < 4; c++) {
                int gn = n0 + tx * 4 + c;
                if (gn < N) Cm[(size_t)gm * N + gn] = alpha * acc[r][c];
            }
        }
    }
}

// ---------------------------------------------------------------------------
// Tiled NT GEMM: C[b] = alpha * A[b](MxK, rm) @ B[b](NxK, rm)^T
// ---------------------------------------------------------------------------
template<int M, int N, int K>
__global__ void gemm_nt(const float* __restrict__ A, size_t sA,
                        const float* __restrict__ Bm, size_t sB,
                        float* __restrict__ Cm, size_t sC, float alpha) {
    const int b = blockIdx.z;
    A  += sA * b;
    Bm += sB * b;
    Cm += sC * b;
    const int m0 = blockIdx.x * 64;
    const int n0 = blockIdx.y * 64;

    __shared__ __align__(16) float As[16][68];  // [k][m]
    __shared__ __align__(16) float Bs[16][68];  // [k][n]

    const int tid = threadIdx.x;
    const int ty = tid >> 4;
    const int tx = tid & 15;

    float acc[4][4] = {};

    for (int k0 = 0; k0 < K; k0 += 16) {
        #pragma unroll
        for (int i = 0; i < 4; i++) {
            int idx = tid + i * 256;
            int r = idx >> 4, k = idx & 15;
            int gm = m0 + r, gk = k0 + k;
            As[k][r] = (gm < M && gk < K) ? A[(size_t)gm * K + gk] : 0.f;
        }
        #pragma unroll
        for (int i = 0; i < 4; i++) {
            int idx = tid + i * 256;
            int n = idx >> 4, k = idx & 15;     // B row-major [N,K]: coalesced over k
            int gn = n0 + n, gk = k0 + k;
            Bs[k][n] = (gn < N && gk < K) ? Bm[(size_t)gn * K + gk] : 0.f;
        }
        __syncthreads();

        #pragma unroll
        for (int kk = 0; kk < 16; kk++) {
            float4 av = *reinterpret_cast<const float4*>(&As[kk][ty * 4]);
            float4 bv = *reinterpret_cast<const float4*>(&Bs[kk][tx * 4]);
            float a[4] = {av.x, av.y, av.z, av.w};
            float bb[4] = {bv.x, bv.y, bv.z, bv.w};
            #pragma unroll
            for (int r = 0; r < 4; r++)
                #pragma unroll
                for (int c = 0; c < 4; c++)
                    acc[r][c] += a[r] * bb[c];
        }
        __syncthreads();
    }

    #pragma unroll
    for (int r = 0; r < 4; r++) {
        int gm = m0 + ty * 4 + r;
        if (gm < M) {
            #pragma unroll
            for (int c = 0; c < 4; c++) {
                int gn = n0 + tx * 4 + c;
                if (gn < N) Cm[(size_t)gm * N + gn] = alpha * acc[r][c];
            }
        }
    }
}

// ---------------------------------------------------------------------------
// Row softmax over last dim (T_) of g_L, in place. One block per row.
// ---------------------------------------------------------------------------
__global__ void softmax_rows() {
    const int c = blockIdx.x;   // 0..CN-1
    const int b = blockIdx.y;   // 0..B_-1
    float* p = g_L + ((size_t)b * CN + c) * T_;
    const int tid = threadIdx.x;
    const int lane = tid & 31, warp = tid >> 5;
    __shared__ float red[8];

    // 1) max
    float m = -CUDART_INF_F;
    for (int i = tid; i < T_; i += 256) m = fmaxf(m, p[i]);
    #pragma unroll
    for (int o = 16; o > 0; o >>= 1) m = fmaxf(m, __shfl_xor_sync(0xffffffffu, m, o));
    if (lane == 0) red[warp] = m;
    __syncthreads();
    float mm = red[0];
    #pragma unroll
    for (int j = 1; j < 8; j++) mm = fmaxf(mm, red[j]);
    __syncthreads();

    // 2) exp + sum
    float s = 0.f;
    for (int i = tid; i < T_; i += 256) {
        float e = __expf(p[i] - mm);
        p[i] = e;
        s += e;
    }
    #pragma unroll
    for (int o = 16; o > 0; o >>= 1) s += __shfl_xor_sync(0xffffffffu, s, o);
    if (lane == 0) red[warp] = s;
    __syncthreads();
    float ss = red[0];
    #pragma unroll
    for (int j = 1; j < 8; j++) ss += red[j];
    float inv = __frcp_rn(ss);

    // 3) normalize
    for (int i = tid; i < T_; i += 256) p[i] *= inv;
}

// ---------------------------------------------------------------------------

static inline int cdiv(int a, int b) { return (a + b - 1) / b; }

extern "C" void kernel_launch(void* const* d_in, const int* in_sizes, int n_in,
                              void* d_out, int out_size) {
    const float* X  = (const float*)d_in[0];  // [B,T,XD]
    const float* H  = (const float*)d_in[1];  // [B,T,HD]
    const float* W1 = (const float*)d_in[2];  // [XD,HD]
    const float* W2 = (const float*)d_in[3];  // [CN,T]
    float* out = (float*)d_out;               // [B,CN,HD]

    float* Z = nullptr; float* Y = nullptr; float* L = nullptr;
    cudaGetSymbolAddress((void**)&Z, g_Z);
    cudaGetSymbolAddress((void**)&Y, g_Y);
    cudaGetSymbolAddress((void**)&L, g_L);

    const float scale = 1.0f / sqrtf((float)XD * (float)HD);

    // 1) Z[b] = W2 @ X[b]                 [CN,T_] x [T_,XD] -> [CN,XD]
    gemm_nn<CN, XD, T_><<<dim3(cdiv(CN,64), cdiv(XD,64), B_), 256>>>(
        W2, 0, X, (size_t)T_ * XD, Z, (size_t)CN * XD, 1.0f);

    // 2) Y[b] = Z[b] @ W1                 [CN,XD] x [XD,HD] -> [CN,HD]
    gemm_nn<CN, HD, XD><<<dim3(cdiv(CN,64), cdiv(HD,64), B_), 256>>>(
        Z, (size_t)CN * XD, W1, 0, Y, (size_t)CN * HD, 1.0f);

    // 3) L[b] = scale * Y[b] @ H[b]^T     [CN,HD] x [T_,HD]^T -> [CN,T_]
    gemm_nt<CN, T_, HD><<<dim3(cdiv(CN,64), cdiv(T_,64), B_), 256>>>(
        Y, (size_t)CN * HD, H, (size_t)T_ * HD, L, (size_t)CN * T_, scale);

    // 4) softmax rows of L
    softmax_rows<<<dim3(CN, B_), 256>>>();

    // 5) out[b] = P[b] @ H[b]             [CN,T_] x [T_,HD] -> [CN,HD]
    gemm_nn<CN, HD, T_><<<dim3(cdiv(CN,64), cdiv(HD,64), B_), 256>>>(
        L, (size_t)CN * T_, H, (size_t)T_ * HD, out, (size_t)CN * HD, 1.0f);
}

// round 3
// speedup vs baseline: 1.1146x; 1.1146x over previous
#include <cuda_runtime.h>
#include <math_constants.h>
#include <cstdint>

#define B_  64
#define T_  1380
#define XD  96
#define HD  192
#define CN  345

// Scratch (device globals; no allocation allowed)
__device__ float g_Z[(size_t)B_ * CN * XD];   // Z = W2 @ X        [B,CN,XD]
__device__ float g_Y[(size_t)B_ * CN * HD];   // Y = Z @ W1        [B,CN,HD]
__device__ float g_L[(size_t)B_ * CN * T_];   // logits/probs      [B,CN,T]

__device__ __forceinline__ uint32_t to_tf32(float x) {
    uint32_t r;
    asm("cvt.rna.tf32.f32 %0, %1;" : "=r"(r) : "f"(x));
    return r;
}

__device__ __forceinline__ void mma_tf32(float* c, const uint32_t* a, const uint32_t* b) {
    asm volatile(
        "mma.sync.aligned.m16n8k8.row.col.f32.tf32.tf32.f32 "
        "{%0,%1,%2,%3}, {%4,%5,%6,%7}, {%8,%9}, {%0,%1,%2,%3};"
        : "+f"(c[0]), "+f"(c[1]), "+f"(c[2]), "+f"(c[3])
        : "r"(a[0]), "r"(a[1]), "r"(a[2]), "r"(a[3]),
          "r"(b[0]), "r"(b[1]));
}

// ---------------------------------------------------------------------------
// tf32 tensor-core GEMM, optionally with 3xTF32 split-precision compensation.
//   C[b] = alpha * A[b] (MxK, row-major) @ opB
//   BNN=true : B is [K,N] row-major (NN)
//   BNN=false: B is [N,K] row-major, used transposed (NT)
// BM=128, BN=64, BK=32, 256 threads (8 warps, 4x2), warp tile 32x32.
// smem (dynamic):
//   A : [m][k] pitch 36 (hi, then lo if SPLIT)
//   B : NT -> [n][k] pitch 36 ; NN -> [k][n] pitch 72 (hi, then lo if SPLIT)
// ---------------------------------------------------------------------------
template<bool BNN, bool SPLIT>
__global__ __launch_bounds__(256)
void gemm_tf32(const float* __restrict__ A, size_t sA,
               const float* __restrict__ Bm, size_t sB,
               float* __restrict__ Cm, size_t sC,
               int M, int N, int K, float alpha)
{
    constexpr int BM = 128, BN = 64, BK = 32;
    constexpr int PA = 36;
    constexpr int ASZ = BM * PA;     // 4608
    constexpr int BSZ = 2304;

    extern __shared__ uint32_t smem[];
    uint32_t* Ah = smem;
    uint32_t* Al = SPLIT ? (Ah + ASZ) : Ah;
    uint32_t* Bh = Ah + (SPLIT ? 2 : 1) * ASZ;
    uint32_t* Bl = SPLIT ? (Bh + BSZ) : Bh;

    const int b = blockIdx.z;
    A  += sA * b;
    Bm += sB * b;
    Cm += sC * b;
    const int m0 = blockIdx.x * BM;
    const int n0 = blockIdx.y * BN;
    const int tid  = threadIdx.x;
    const int warp = tid >> 5, lane = tid & 31;
    const int wm = warp >> 1, wn = warp & 1;   // 4 x 2 warp grid
    const int l4 = lane >> 2, lk = lane & 3;

    float acc[2][4][4];
    #pragma unroll
    for (int i = 0; i < 2; i++)
        #pragma unroll
        for (int j = 0; j < 4; j++)
            #pragma unroll
            for (int q = 0; q < 4; q++) acc[i][j][q] = 0.f;

    for (int k0 = 0; k0 < K; k0 += BK) {
        // ---- load A tile: 128x32, float4 ----
        #pragma unroll
        for (int i = 0; i < 4; i++) {
            int idx = tid + i * 256;
            int r = idx >> 3, c4 = idx & 7;
            int gm = m0 + r, gk = k0 + c4 * 4;
            float4 v = make_float4(0.f, 0.f, 0.f, 0.f);
            if (gm < M && gk + 4 <= K)
                v = *reinterpret_cast<const float4*>(A + (size_t)gm * K + gk);
            float vv[4] = {v.x, v.y, v.z, v.w};
            #pragma unroll
            for (int q = 0; q < 4; q++) {
                uint32_t hi = to_tf32(vv[q]);
                Ah[r * PA + c4 * 4 + q] = hi;
                if (SPLIT)
                    Al[r * PA + c4 * 4 + q] = to_tf32(vv[q] - __uint_as_float(hi));
            }
        }
        // ---- load B tile ----
        if (BNN) {
            int kp = tid >> 6;       // 0..3
            int n  = tid & 63;
            #pragma unroll
            for (int i = 0; i < 8; i++) {
                int k = kp + i * 4;
                int gk = k0 + k, gn = n0 + n;
                float v = (gk < K && gn < N) ? Bm[(size_t)gk * N + gn] : 0.f;
                uint32_t hi = to_tf32(v);
                Bh[k * 72 + n] = hi;
                if (SPLIT)
                    Bl[k * 72 + n] = to_tf32(v - __uint_as_float(hi));
            }
        } else {
            #pragma unroll
            for (int i = 0; i < 2; i++) {
                int idx = tid + i * 256;
                int r = idx >> 3, c4 = idx & 7;
                int gn = n0 + r, gk = k0 + c4 * 4;
                float4 v = make_float4(0.f, 0.f, 0.f, 0.f);
                if (gn < N && gk + 4 <= K)
                    v = *reinterpret_cast<const float4*>(Bm + (size_t)gn * K + gk);
                float vv[4] = {v.x, v.y, v.z, v.w};
                #pragma unroll
                for (int q = 0; q < 4; q++) {
                    uint32_t hi = to_tf32(vv[q]);
                    Bh[r * 36 + c4 * 4 + q] = hi;
                    if (SPLIT)
                        Bl[r * 36 + c4 * 4 + q] = to_tf32(vv[q] - __uint_as_float(hi));
                }
            }
        }
        __syncthreads();

        #pragma unroll
        for (int kk = 0; kk < BK; kk += 8) {
            uint32_t ah[2][4], bh[4][2];
            #pragma unroll
            for (int mi = 0; mi < 2; mi++) {
                int rb = wm * 32 + mi * 16 + l4;
                ah[mi][0] = Ah[rb * PA + kk + lk];
                ah[mi][1] = Ah[(rb + 8) * PA + kk + lk];
                ah[mi][2] = Ah[rb * PA + kk + lk + 4];
                ah[mi][3] = Ah[(rb + 8) * PA + kk + lk + 4];
            }
            #pragma unroll
            for (int ni = 0; ni < 4; ni++) {
                int nb = wn * 32 + ni * 8 + l4;
                if (BNN) {
                    bh[ni][0] = Bh[(kk + lk) * 72 + nb];
                    bh[ni][1] = Bh[(kk + lk + 4) * 72 + nb];
                } else {
                    bh[ni][0] = Bh[nb * 36 + kk + lk];
                    bh[ni][1] = Bh[nb * 36 + kk + lk + 4];
                }
            }
            // hi * hi
            #pragma unroll
            for (int mi = 0; mi < 2; mi++)
                #pragma unroll
                for (int ni = 0; ni < 4; ni++)
                    mma_tf32(acc[mi][ni], ah[mi], bh[ni]);

            if (SPLIT) {
                uint32_t al[2][4], bl[4][2];
                #pragma unroll
                for (int mi = 0; mi < 2; mi++) {
                    int rb = wm * 32 + mi * 16 + l4;
                    al[mi][0] = Al[rb * PA + kk + lk];
                    al[mi][1] = Al[(rb + 8) * PA + kk + lk];
                    al[mi][2] = Al[rb * PA + kk + lk + 4];
                    al[mi][3] = Al[(rb + 8) * PA + kk + lk + 4];
                }
                #pragma unroll
                for (int ni = 0; ni < 4; ni++) {
                    int nb = wn * 32 + ni * 8 + l4;
                    if (BNN) {
                        bl[ni][0] = Bl[(kk + lk) * 72 + nb];
                        bl[ni][1] = Bl[(kk + lk + 4) * 72 + nb];
                    } else {
                        bl[ni][0] = Bl[nb * 36 + kk + lk];
                        bl[ni][1] = Bl[nb * 36 + kk + lk + 4];
                    }
                }
                // hi * lo  +  lo * hi
                #pragma unroll
                for (int mi = 0; mi < 2; mi++)
                    #pragma unroll
                    for (int ni = 0; ni < 4; ni++) {
                        mma_tf32(acc[mi][ni], ah[mi], bl[ni]);
                        mma_tf32(acc[mi][ni], al[mi], bh[ni]);
                    }
            }
        }
        __syncthreads();
    }

    // ---- epilogue ----
    #pragma unroll
    for (int mi = 0; mi < 2; mi++) {
        #pragma unroll
        for (int ni = 0; ni < 4; ni++) {
            int r0 = m0 + wm * 32 + mi * 16 + l4;
            int c0 = n0 + wn * 32 + ni * 8 + 2 * lk;
            if (c0 < N) {
                if (r0 < M) {
                    float2 v = make_float2(alpha * acc[mi][ni][0], alpha * acc[mi][ni][1]);
                    *reinterpret_cast<float2*>(Cm + (size_t)r0 * N + c0) = v;
                }
                if (r0 + 8 < M) {
                    float2 v = make_float2(alpha * acc[mi][ni][2], alpha * acc[mi][ni][3]);
                    *reinterpret_cast<float2*>(Cm + (size_t)(r0 + 8) * N + c0) = v;
                }
            }
        }
    }
}

// ---------------------------------------------------------------------------
// Row softmax over last dim (T_) of g_L, in place. One block per row, float4.
// ---------------------------------------------------------------------------
__global__ void softmax_rows() {
    const size_t row = (size_t)blockIdx.y * CN + blockIdx.x;
    float4* p = reinterpret_cast<float4*>(g_L + row * T_);
    constexpr int N4 = T_ / 4;   // 345
    const int tid = threadIdx.x;
    const int lane = tid & 31, warp = tid >> 5;
    __shared__ float red[8];

    float m = -CUDART_INF_F;
    for (int i = tid; i < N4; i += 256) {
        float4 v = p[i];
        m = fmaxf(m, fmaxf(fmaxf(v.x, v.y), fmaxf(v.z, v.w)));
    }
    #pragma unroll
    for (int o = 16; o > 0; o >>= 1) m = fmaxf(m, __shfl_xor_sync(0xffffffffu, m, o));
    if (lane == 0) red[warp] = m;
    __syncthreads();
    float mm = red[0];
    #pragma unroll
    for (int j = 1; j < 8; j++) mm = fmaxf(mm, red[j]);
    __syncthreads();

    float s = 0.f;
    for (int i = tid; i < N4; i += 256) {
        float4 v = p[i];
        v.x = __expf(v.x - mm); v.y = __expf(v.y - mm);
        v.z = __expf(v.z - mm); v.w = __expf(v.w - mm);
        p[i] = v;
        s += (v.x + v.y) + (v.z + v.w);
    }
    #pragma unroll
    for (int o = 16; o > 0; o >>= 1) s += __shfl_xor_sync(0xffffffffu, s, o);
    if (lane == 0) red[warp] = s;
    __syncthreads();
    float ss = red[0];
    #pragma unroll
    for (int j = 1; j < 8; j++) ss += red[j];
    float inv = __frcp_rn(ss);

    for (int i = tid; i < N4; i += 256) {
        float4 v = p[i];
        v.x *= inv; v.y *= inv; v.z *= inv; v.w *= inv;
        p[i] = v;
    }
}

// ---------------------------------------------------------------------------

static inline int cdiv(int a, int b) { return (a + b - 1) / b; }

extern "C" void kernel_launch(void* const* d_in, const int* in_sizes, int n_in,
                              void* d_out, int out_size) {
    const float* X  = (const float*)d_in[0];  // [B,T,XD]
    const float* H  = (const float*)d_in[1];  // [B,T,HD]
    const float* W1 = (const float*)d_in[2];  // [XD,HD]
    const float* W2 = (const float*)d_in[3];  // [CN,T]
    float* out = (float*)d_out;               // [B,CN,HD]

    float* Z = nullptr; float* Y = nullptr; float* L = nullptr;
    cudaGetSymbolAddress((void**)&Z, g_Z);
    cudaGetSymbolAddress((void**)&Y, g_Y);
    cudaGetSymbolAddress((void**)&L, g_L);

    const float scale = 1.0f / sqrtf((float)XD * (float)HD);

    constexpr int SM_SINGLE = (4608 + 2304) * 4;       // 27648 B
    constexpr int SM_SPLIT  = (2*4608 + 2*2304) * 4;   // 55296 B

    static bool attr_done = false;
    if (!attr_done) {
        cudaFuncSetAttribute(gemm_tf32<true, true>,
            cudaFuncAttributeMaxDynamicSharedMemorySize, SM_SPLIT);
        cudaFuncSetAttribute(gemm_tf32<false, true>,
            cudaFuncAttributeMaxDynamicSharedMemorySize, SM_SPLIT);
        cudaFuncSetAttribute(gemm_tf32<true, false>,
            cudaFuncAttributeMaxDynamicSharedMemorySize, SM_SINGLE);
        attr_done = true;
    }

    // 1) Z[b] = W2 @ X[b]          [CN,T] x [T,XD] -> [CN,XD]   (NN, 3xTF32)
    gemm_tf32<true, true><<<dim3(cdiv(CN,128), cdiv(XD,64), B_), 256, SM_SPLIT>>>(
        W2, 0, X, (size_t)T_ * XD, Z, (size_t)CN * XD, CN, XD, T_, 1.0f);

    // 2) Y[b] = Z[b] @ W1          [CN,XD] x [XD,HD] -> [CN,HD] (NN, 3xTF32)
    gemm_tf32<true, true><<<dim3(cdiv(CN,128), cdiv(HD,64), B_), 256, SM_SPLIT>>>(
        Z, (size_t)CN * XD, W1, 0, Y, (size_t)CN * HD, CN, HD, XD, 1.0f);

    // 3) L[b] = scale * Y[b] @ H[b]^T   [CN,HD] x [T,HD]^T -> [CN,T]  (NT, 3xTF32)
    gemm_tf32<false, true><<<dim3(cdiv(CN,128), cdiv(T_,64), B_), 256, SM_SPLIT>>>(
        Y, (size_t)CN * HD, H, (size_t)T_ * HD, L, (size_t)CN * T_, CN, T_, HD, scale);

    // 4) softmax rows of L
    softmax_rows<<<dim3(CN, B_), 256>>>();

    // 5) out[b] = P[b] @ H[b]      [CN,T] x [T,HD] -> [CN,HD]  (NN, single tf32)
    gemm_tf32<true, false><<<dim3(cdiv(CN,128), cdiv(HD,64), B_), 256, SM_SINGLE>>>(
        L, (size_t)CN * T_, H, (size_t)T_ * HD, out, (size_t)CN * HD, CN, HD, T_, 1.0f);
}

// round 4
// speedup vs baseline: 1.5627x; 1.4021x over previous
#include <cuda_runtime.h>
#include <math_constants.h>
#include <cstdint>

#define B_  64
#define T_  1380
#define XD  96
#define HD  192
#define CN  345

// Scratch (device globals; no allocation allowed)
__device__ float g_Z[(size_t)B_ * CN * XD];   // Z = W2 @ X        [B,CN,XD]
__device__ float g_Y[(size_t)B_ * CN * HD];   // Y = Z @ W1        [B,CN,HD]
__device__ float g_L[(size_t)B_ * CN * T_];   // logits/probs      [B,CN,T]

__device__ __forceinline__ uint32_t to_tf32(float x) {
    uint32_t r;
    asm("cvt.rna.tf32.f32 %0, %1;" : "=r"(r) : "f"(x));
    return r;
}

__device__ __forceinline__ void mma_tf32(float* c, const uint32_t* a, const uint32_t* b) {
    asm volatile(
        "mma.sync.aligned.m16n8k8.row.col.f32.tf32.tf32.f32 "
        "{%0,%1,%2,%3}, {%4,%5,%6,%7}, {%8,%9}, {%0,%1,%2,%3};"
        : "+f"(c[0]), "+f"(c[1]), "+f"(c[2]), "+f"(c[3])
        : "r"(a[0]), "r"(a[1]), "r"(a[2]), "r"(a[3]),
          "r"(b[0]), "r"(b[1]));
}

// ---------------------------------------------------------------------------
// tf32 tensor-core GEMM, optionally with 3xTF32 split-precision compensation.
//   C[b] = alpha * A[b] (MxK, row-major) @ opB
//   BNN=true : B is [K,N] row-major (NN)
//   BNN=false: B is [N,K] row-major, used transposed (NT)
// BM=128, BN=64, BK=32, 256 threads (8 warps, 4x2), warp tile 32x32.
// smem (dynamic):
//   A : [m][k] pitch 36 (hi, then lo if SPLIT)
//   B : NT -> [n][k] pitch 36 ; NN -> [k][n] pitch 72 (hi, then lo if SPLIT)
// ---------------------------------------------------------------------------
template<bool BNN, bool SPLIT>
__global__ __launch_bounds__(256)
void gemm_tf32(const float* __restrict__ A, size_t sA,
               const float* __restrict__ Bm, size_t sB,
               float* __restrict__ Cm, size_t sC,
               int M, int N, int K, float alpha)
{
    constexpr int BM = 128, BN = 64, BK = 32;
    constexpr int PA = 36;
    constexpr int ASZ = BM * PA;     // 4608
    constexpr int BSZ = 2304;

    extern __shared__ uint32_t smem[];
    uint32_t* Ah = smem;
    uint32_t* Al = SPLIT ? (Ah + ASZ) : Ah;
    uint32_t* Bh = Ah + (SPLIT ? 2 : 1) * ASZ;
    uint32_t* Bl = SPLIT ? (Bh + BSZ) : Bh;

    const int b = blockIdx.z;
    A  += sA * b;
    Bm += sB * b;
    Cm += sC * b;
    const int m0 = blockIdx.x * BM;
    const int n0 = blockIdx.y * BN;
    const int tid  = threadIdx.x;
    const int warp = tid >> 5, lane = tid & 31;
    const int wm = warp >> 1, wn = warp & 1;   // 4 x 2 warp grid
    const int l4 = lane >> 2, lk = lane & 3;

    float acc[2][4][4];
    #pragma unroll
    for (int i = 0; i < 2; i++)
        #pragma unroll
        for (int j = 0; j < 4; j++)
            #pragma unroll
            for (int q = 0; q < 4; q++) acc[i][j][q] = 0.f;

    for (int k0 = 0; k0 < K; k0 += BK) {
        // ---- load A tile: 128x32, float4 ----
        #pragma unroll
        for (int i = 0; i < 4; i++) {
            int idx = tid + i * 256;
            int r = idx >> 3, c4 = idx & 7;
            int gm = m0 + r, gk = k0 + c4 * 4;
            float4 v = make_float4(0.f, 0.f, 0.f, 0.f);
            if (gm < M && gk + 4 <= K)
                v = *reinterpret_cast<const float4*>(A + (size_t)gm * K + gk);
            float vv[4] = {v.x, v.y, v.z, v.w};
            #pragma unroll
            for (int q = 0; q < 4; q++) {
                uint32_t hi = to_tf32(vv[q]);
                Ah[r * PA + c4 * 4 + q] = hi;
                if (SPLIT)
                    Al[r * PA + c4 * 4 + q] = to_tf32(vv[q] - __uint_as_float(hi));
            }
        }
        // ---- load B tile ----
        if (BNN) {
            int kp = tid >> 6;       // 0..3
            int n  = tid & 63;
            #pragma unroll
            for (int i = 0; i < 8; i++) {
                int k = kp + i * 4;
                int gk = k0 + k, gn = n0 + n;
                float v = (gk < K && gn < N) ? Bm[(size_t)gk * N + gn] : 0.f;
                uint32_t hi = to_tf32(v);
                Bh[k * 72 + n] = hi;
                if (SPLIT)
                    Bl[k * 72 + n] = to_tf32(v - __uint_as_float(hi));
            }
        } else {
            #pragma unroll
            for (int i = 0; i < 2; i++) {
                int idx = tid + i * 256;
                int r = idx >> 3, c4 = idx & 7;
                int gn = n0 + r, gk = k0 + c4 * 4;
                float4 v = make_float4(0.f, 0.f, 0.f, 0.f);
                if (gn < N && gk + 4 <= K)
                    v = *reinterpret_cast<const float4*>(Bm + (size_t)gn * K + gk);
                float vv[4] = {v.x, v.y, v.z, v.w};
                #pragma unroll
                for (int q = 0; q < 4; q++) {
                    uint32_t hi = to_tf32(vv[q]);
                    Bh[r * 36 + c4 * 4 + q] = hi;
                    if (SPLIT)
                        Bl[r * 36 + c4 * 4 + q] = to_tf32(vv[q] - __uint_as_float(hi));
                }
            }
        }
        __syncthreads();

        #pragma unroll
        for (int kk = 0; kk < BK; kk += 8) {
            uint32_t ah[2][4], bh[4][2];
            #pragma unroll
            for (int mi = 0; mi < 2; mi++) {
                int rb = wm * 32 + mi * 16 + l4;
                ah[mi][0] = Ah[rb * PA + kk + lk];
                ah[mi][1] = Ah[(rb + 8) * PA + kk + lk];
                ah[mi][2] = Ah[rb * PA + kk + lk + 4];
                ah[mi][3] = Ah[(rb + 8) * PA + kk + lk + 4];
            }
            #pragma unroll
            for (int ni = 0; ni < 4; ni++) {
                int nb = wn * 32 + ni * 8 + l4;
                if (BNN) {
                    bh[ni][0] = Bh[(kk + lk) * 72 + nb];
                    bh[ni][1] = Bh[(kk + lk + 4) * 72 + nb];
                } else {
                    bh[ni][0] = Bh[nb * 36 + kk + lk];
                    bh[ni][1] = Bh[nb * 36 + kk + lk + 4];
                }
            }
            // hi * hi
            #pragma unroll
            for (int mi = 0; mi < 2; mi++)
                #pragma unroll
                for (int ni = 0; ni < 4; ni++)
                    mma_tf32(acc[mi][ni], ah[mi], bh[ni]);

            if (SPLIT) {
                uint32_t al[2][4], bl[4][2];
                #pragma unroll
                for (int mi = 0; mi < 2; mi++) {
                    int rb = wm * 32 + mi * 16 + l4;
                    al[mi][0] = Al[rb * PA + kk + lk];
                    al[mi][1] = Al[(rb + 8) * PA + kk + lk];
                    al[mi][2] = Al[rb * PA + kk + lk + 4];
                    al[mi][3] = Al[(rb + 8) * PA + kk + lk + 4];
                }
                #pragma unroll
                for (int ni = 0; ni < 4; ni++) {
                    int nb = wn * 32 + ni * 8 + l4;
                    if (BNN) {
                        bl[ni][0] = Bl[(kk + lk) * 72 + nb];
                        bl[ni][1] = Bl[(kk + lk + 4) * 72 + nb];
                    } else {
                        bl[ni][0] = Bl[nb * 36 + kk + lk];
                        bl[ni][1] = Bl[nb * 36 + kk + lk + 4];
                    }
                }
                // hi * lo  +  lo * hi
                #pragma unroll
                for (int mi = 0; mi < 2; mi++)
                    #pragma unroll
                    for (int ni = 0; ni < 4; ni++) {
                        mma_tf32(acc[mi][ni], ah[mi], bl[ni]);
                        mma_tf32(acc[mi][ni], al[mi], bh[ni]);
                    }
            }
        }
        __syncthreads();
    }

    // ---- epilogue ----
    #pragma unroll
    for (int mi = 0; mi < 2; mi++) {
        #pragma unroll
        for (int ni = 0; ni < 4; ni++) {
            int r0 = m0 + wm * 32 + mi * 16 + l4;
            int c0 = n0 + wn * 32 + ni * 8 + 2 * lk;
            if (c0 < N) {
                if (r0 < M) {
                    float2 v = make_float2(alpha * acc[mi][ni][0], alpha * acc[mi][ni][1]);
                    *reinterpret_cast<float2*>(Cm + (size_t)r0 * N + c0) = v;
                }
                if (r0 + 8 < M) {
                    float2 v = make_float2(alpha * acc[mi][ni][2], alpha * acc[mi][ni][3]);
                    *reinterpret_cast<float2*>(Cm + (size_t)(r0 + 8) * N + c0) = v;
                }
            }
        }
    }
}

// ---------------------------------------------------------------------------
// Row softmax over last dim (T_) of g_L, in place. One block per row, float4.
// ---------------------------------------------------------------------------
__global__ void softmax_rows() {
    const size_t row = (size_t)blockIdx.y * CN + blockIdx.x;
    float4* p = reinterpret_cast<float4*>(g_L + row * T_);
    constexpr int N4 = T_ / 4;   // 345
    const int tid = threadIdx.x;
    const int lane = tid & 31, warp = tid >> 5;
    __shared__ float red[8];

    float m = -CUDART_INF_F;
    for (int i = tid; i < N4; i += 256) {
        float4 v = p[i];
        m = fmaxf(m, fmaxf(fmaxf(v.x, v.y), fmaxf(v.z, v.w)));
    }
    #pragma unroll
    for (int o = 16; o > 0; o >>= 1) m = fmaxf(m, __shfl_xor_sync(0xffffffffu, m, o));
    if (lane == 0) red[warp] = m;
    __syncthreads();
    float mm = red[0];
    #pragma unroll
    for (int j = 1; j < 8; j++) mm = fmaxf(mm, red[j]);
    __syncthreads();

    float s = 0.f;
    for (int i = tid; i < N4; i += 256) {
        float4 v = p[i];
        v.x = __expf(v.x - mm); v.y = __expf(v.y - mm);
        v.z = __expf(v.z - mm); v.w = __expf(v.w - mm);
        p[i] = v;
        s += (v.x + v.y) + (v.z + v.w);
    }
    #pragma unroll
    for (int o = 16; o > 0; o >>= 1) s += __shfl_xor_sync(0xffffffffu, s, o);
    if (lane == 0) red[warp] = s;
    __syncthreads();
    float ss = red[0];
    #pragma unroll
    for (int j = 1; j < 8; j++) ss += red[j];
    float inv = __frcp_rn(ss);

    for (int i = tid; i < N4; i += 256) {
        float4 v = p[i];
        v.x *= inv; v.y *= inv; v.z *= inv; v.w *= inv;
        p[i] = v;
    }
}

// ---------------------------------------------------------------------------

static inline int cdiv(int a, int b) { return (a + b - 1) / b; }

extern "C" void kernel_launch(void* const* d_in, const int* in_sizes, int n_in,
                              void* d_out, int out_size) {
    const float* X  = (const float*)d_in[0];  // [B,T,XD]
    const float* H  = (const float*)d_in[1];  // [B,T,HD]
    const float* W1 = (const float*)d_in[2];  // [XD,HD]
    const float* W2 = (const float*)d_in[3];  // [CN,T]
    float* out = (float*)d_out;               // [B,CN,HD]

    float* Z = nullptr; float* Y = nullptr; float* L = nullptr;
    cudaGetSymbolAddress((void**)&Z, g_Z);
    cudaGetSymbolAddress((void**)&Y, g_Y);
    cudaGetSymbolAddress((void**)&L, g_L);

    const float scale = 1.0f / sqrtf((float)XD * (float)HD);

    constexpr int SM_SINGLE = (4608 + 2304) * 4;       // 27648 B
    constexpr int SM_SPLIT  = (2*4608 + 2*2304) * 4;   // 55296 B

    static bool attr_done = false;
    if (!attr_done) {
        cudaFuncSetAttribute(gemm_tf32<true, true>,
            cudaFuncAttributeMaxDynamicSharedMemorySize, SM_SPLIT);
        cudaFuncSetAttribute(gemm_tf32<false, true>,
            cudaFuncAttributeMaxDynamicSharedMemorySize, SM_SPLIT);
        cudaFuncSetAttribute(gemm_tf32<true, false>,
            cudaFuncAttributeMaxDynamicSharedMemorySize, SM_SINGLE);
        attr_done = true;
    }

    // 1) Z[b] = W2 @ X[b]          [CN,T] x [T,XD] -> [CN,XD]   (NN, 3xTF32)
    gemm_tf32<true, true><<<dim3(cdiv(CN,128), cdiv(XD,64), B_), 256, SM_SPLIT>>>(
        W2, 0, X, (size_t)T_ * XD, Z, (size_t)CN * XD, CN, XD, T_, 1.0f);

    // 2) Y[b] = Z[b] @ W1          [CN,XD] x [XD,HD] -> [CN,HD] (NN, 3xTF32)
    gemm_tf32<true, true><<<dim3(cdiv(CN,128), cdiv(HD,64), B_), 256, SM_SPLIT>>>(
        Z, (size_t)CN * XD, W1, 0, Y, (size_t)CN * HD, CN, HD, XD, 1.0f);

    // 3) L[b] = scale * Y[b] @ H[b]^T   [CN,HD] x [T,HD]^T -> [CN,T]  (NT, 3xTF32)
    gemm_tf32<false, true><<<dim3(cdiv(CN,128), cdiv(T_,64), B_), 256, SM_SPLIT>>>(
        Y, (size_t)CN * HD, H, (size_t)T_ * HD, L, (size_t)CN * T_, CN, T_, HD, scale);

    // 4) softmax rows of L
    softmax_rows<<<dim3(CN, B_), 256>>>();

    // 5) out[b] = P[b] @ H[b]      [CN,T] x [T,HD] -> [CN,HD]  (NN, single tf32)
    gemm_tf32<true, false><<<dim3(cdiv(CN,128), cdiv(HD,64), B_), 256, SM_SINGLE>>>(
        L, (size_t)CN * T_, H, (size_t)T_ * HD, out, (size_t)CN * HD, CN, HD, T_, 1.0f);
}

// round 6
// speedup vs baseline: 1.9574x; 1.2525x over previous
#include <cuda_runtime.h>
#include <math_constants.h>
#include <cstdint>

#define B_  64
#define T_  1380
#define XD  96
#define HD  192
#define CN  345

// Scratch (device globals; no allocation allowed)
__device__ float g_Z[(size_t)B_ * CN * XD];   // Z = W2 @ X        [B,CN,XD]
__device__ float g_Y[(size_t)B_ * CN * HD];   // Y = Z @ W1        [B,CN,HD]
__device__ float g_L[(size_t)B_ * CN * T_];   // logits/probs      [B,CN,T]

__device__ __forceinline__ uint32_t to_tf32(float x) {
    uint32_t r;
    asm("cvt.rna.tf32.f32 %0, %1;" : "=r"(r) : "f"(x));
    return r;
}

__device__ __forceinline__ void mma_tf32(float* c, const uint32_t* a, const uint32_t* b) {
    asm volatile(
        "mma.sync.aligned.m16n8k8.row.col.f32.tf32.tf32.f32 "
        "{%0,%1,%2,%3}, {%4,%5,%6,%7}, {%8,%9}, {%0,%1,%2,%3};"
        : "+f"(c[0]), "+f"(c[1]), "+f"(c[2]), "+f"(c[3])
        : "r"(a[0]), "r"(a[1]), "r"(a[2]), "r"(a[3]),
          "r"(b[0]), "r"(b[1]));
}

// 16B cp.async with zero-fill when !ok (src clamped by caller)
__device__ __forceinline__ void cp16(uint32_t dst, const void* src, bool ok) {
    asm volatile(
        "{\n\t.reg .pred p;\n\t.reg .b32 sz;\n\t"
        "setp.ne.u32 p, %2, 0;\n\t"
        "selp.b32 sz, 16, 0, p;\n\t"
        "cp.async.cg.shared.global [%0], [%1], 16, sz;\n\t}"
        :: "r"(dst), "l"(src), "r"((uint32_t)ok) : "memory");
}
#define CP_COMMIT() asm volatile("cp.async.commit_group;" ::: "memory")

// ---------------------------------------------------------------------------
// tf32 tensor-core GEMM, cp.async double-buffered, split-precision in regs.
//   C[b] = alpha * A[b] (MxK, row-major) @ opB
//   BNN=true : B is [K,N] row-major (NN)
//   BNN=false: B is [N,K] row-major, used transposed (NT)
// BM=128, BN=64, BK=32, 256 threads (8 warps, 4x2), warp tile 32x32.
// smem holds RAW fp32 (2 stages):
//   A : [m][k] pitch 36
//   B : NT -> [n][k] pitch 36 ; NN -> [k][n] pitch 72
// SPLIT: 3xTF32 compensation (hi*hi + hi*lo + lo*hi), hi/lo made per-fragment.
// ---------------------------------------------------------------------------
template<bool BNN, bool SPLIT>
__global__ __launch_bounds__(256)
void gemm_tf32(const float* __restrict__ A, size_t sA,
               const float* __restrict__ Bm, size_t sB,
               float* __restrict__ Cm, size_t sC,
               int M, int N, int K, float alpha)
{
    constexpr int BM = 128, BN = 64, BK = 32;
    constexpr int PA = 36;
    constexpr int PB = BNN ? 72 : 36;
    constexpr int ASZ = BM * PA;                  // 4608 floats
    constexpr int BSZ = BNN ? BK * PB : BN * PB;  // 2304 floats
    constexpr int STG = ASZ + BSZ;                // 6912 floats / stage

    extern __shared__ float sm[];

    const int b = blockIdx.z;
    A  += sA * b;
    Bm += sB * b;
    Cm += sC * b;
    const int m0 = blockIdx.x * BM;
    const int n0 = blockIdx.y * BN;
    const int tid  = threadIdx.x;
    const int warp = tid >> 5, lane = tid & 31;
    const int wm = warp >> 1, wn = warp & 1;
    const int l4 = lane >> 2, lk = lane & 3;

    float acc[2][4][4] = {};

    const int nck = (K + BK - 1) / BK;

    auto load_tile = [&](int ck, int st) {
        const int k0 = ck * BK;
        float* As = sm + st * STG;
        float* Bs = As + ASZ;
        #pragma unroll
        for (int i = 0; i < 4; i++) {              // A: 1024 16B chunks
            int idx = tid + i * 256;
            int r = idx >> 3, c4 = idx & 7;
            int gm = m0 + r, gk = k0 + c4 * 4;
            bool ok = (gm < M) && (gk + 4 <= K);
            const float* src = ok ? (A + (size_t)gm * K + gk) : A;
            cp16((uint32_t)__cvta_generic_to_shared(As + r * PA + c4 * 4), src, ok);
        }
        if (BNN) {
            #pragma unroll
            for (int i = 0; i < 2; i++) {          // B: 512 chunks [k][n]
                int idx = tid + i * 256;
                int k = idx >> 4, n4 = idx & 15;
                int gk = k0 + k, gn = n0 + n4 * 4;
                bool ok = (gk < K) && (gn + 4 <= N);
                const float* src = ok ? (Bm + (size_t)gk * N + gn) : Bm;
                cp16((uint32_t)__cvta_generic_to_shared(Bs + k * PB + n4 * 4), src, ok);
            }
        } else {
            #pragma unroll
            for (int i = 0; i < 2; i++) {          // B: 512 chunks [n][k]
                int idx = tid + i * 256;
                int r = idx >> 3, c4 = idx & 7;
                int gn = n0 + r, gk = k0 + c4 * 4;
                bool ok = (gn < N) && (gk + 4 <= K);
                const float* src = ok ? (Bm + (size_t)gn * K + gk) : Bm;
                cp16((uint32_t)__cvta_generic_to_shared(Bs + r * PB + c4 * 4), src, ok);
            }
        }
    };

    load_tile(0, 0);
    CP_COMMIT();

    for (int ck = 0; ck < nck; ck++) {
        if (ck + 1 < nck) {
            load_tile(ck + 1, (ck + 1) & 1);
            CP_COMMIT();
            asm volatile("cp.async.wait_group 1;" ::: "memory");
        } else {
            asm volatile("cp.async.wait_group 0;" ::: "memory");
        }
        __syncthreads();

        const float* As = sm + (ck & 1) * STG;
        const float* Bs = As + ASZ;

        #pragma unroll
        for (int kk = 0; kk < BK; kk += 8) {
            uint32_t ahi[2][4], alo[2][4], bhi[4][2], blo[4][2];
            #pragma unroll
            for (int mi = 0; mi < 2; mi++) {
                int rb = wm * 32 + mi * 16 + l4;
                float x0 = As[rb * PA + kk + lk];
                float x1 = As[(rb + 8) * PA + kk + lk];
                float x2 = As[rb * PA + kk + lk + 4];
                float x3 = As[(rb + 8) * PA + kk + lk + 4];
                ahi[mi][0] = to_tf32(x0); ahi[mi][1] = to_tf32(x1);
                ahi[mi][2] = to_tf32(x2); ahi[mi][3] = to_tf32(x3);
                if (SPLIT) {
                    alo[mi][0] = to_tf32(x0 - __uint_as_float(ahi[mi][0]));
                    alo[mi][1] = to_tf32(x1 - __uint_as_float(ahi[mi][1]));
                    alo[mi][2] = to_tf32(x2 - __uint_as_float(ahi[mi][2]));
                    alo[mi][3] = to_tf32(x3 - __uint_as_float(ahi[mi][3]));
                }
            }
            #pragma unroll
            for (int ni = 0; ni < 4; ni++) {
                int nb = wn * 32 + ni * 8 + l4;
                float y0, y1;
                if (BNN) {
                    y0 = Bs[(kk + lk) * PB + nb];
                    y1 = Bs[(kk + lk + 4) * PB + nb];
                } else {
                    y0 = Bs[nb * PB + kk + lk];
                    y1 = Bs[nb * PB + kk + lk + 4];
                }
                bhi[ni][0] = to_tf32(y0); bhi[ni][1] = to_tf32(y1);
                if (SPLIT) {
                    blo[ni][0] = to_tf32(y0 - __uint_as_float(bhi[ni][0]));
                    blo[ni][1] = to_tf32(y1 - __uint_as_float(bhi[ni][1]));
                }
            }
            #pragma unroll
            for (int mi = 0; mi < 2; mi++)
                #pragma unroll
                for (int ni = 0; ni < 4; ni++)
                    mma_tf32(acc[mi][ni], ahi[mi], bhi[ni]);
            if (SPLIT) {
                #pragma unroll
                for (int mi = 0; mi < 2; mi++)
                    #pragma unroll
                    for (int ni = 0; ni < 4; ni++) {
                        mma_tf32(acc[mi][ni], ahi[mi], blo[ni]);
                        mma_tf32(acc[mi][ni], alo[mi], bhi[ni]);
                    }
            }
        }
        __syncthreads();
    }

    // ---- epilogue ----
    #pragma unroll
    for (int mi = 0; mi < 2; mi++) {
        #pragma unroll
        for (int ni = 0; ni < 4; ni++) {
            int r0 = m0 + wm * 32 + mi * 16 + l4;
            int c0 = n0 + wn * 32 + ni * 8 + 2 * lk;
            if (c0 < N) {
                if (r0 < M) {
                    float2 v = make_float2(alpha * acc[mi][ni][0], alpha * acc[mi][ni][1]);
                    *reinterpret_cast<float2*>(Cm + (size_t)r0 * N + c0) = v;
                }
                if (r0 + 8 < M) {
                    float2 v = make_float2(alpha * acc[mi][ni][2], alpha * acc[mi][ni][3]);
                    *reinterpret_cast<float2*>(Cm + (size_t)(r0 + 8) * N + c0) = v;
                }
            }
        }
    }
}

// ---------------------------------------------------------------------------
// Online 2-pass row softmax over last dim (T_) of g_L, in place.
// Pass 1: single read computing running (max, sum). Pass 2: write exp/sum.
// ---------------------------------------------------------------------------
__global__ void softmax_rows() {
    const size_t row = (size_t)blockIdx.y * CN + blockIdx.x;
    float4* p = reinterpret_cast<float4*>(g_L + row * T_);
    constexpr int N4 = T_ / 4;   // 345
    const int tid = threadIdx.x;
    const int lane = tid & 31, warp = tid >> 5;
    __shared__ float rm[8], rs[8];

    float m = -CUDART_INF_F, s = 0.f;
    for (int i = tid; i < N4; i += 256) {
        float4 v = p[i];
        float xs[4] = {v.x, v.y, v.z, v.w};
        #pragma unroll
        for (int q = 0; q < 4; q++) {
            float x = xs[q];
            if (x <= m) {
                s += __expf(x - m);
            } else {
                s = s * __expf(m - x) + 1.f;
                m = x;
            }
        }
    }
    #pragma unroll
    for (int o = 16; o > 0; o >>= 1) {
        float om = __shfl_xor_sync(0xffffffffu, m, o);
        float os = __shfl_xor_sync(0xffffffffu, s, o);
        float nm = fmaxf(m, om);
        s = s * __expf(m - nm) + os * __expf(om - nm);
        m = nm;
    }
    if (lane == 0) { rm[warp] = m; rs[warp] = s; }
    __syncthreads();
    float M = rm[0], S = rs[0];
    #pragma unroll
    for (int j = 1; j < 8; j++) {
        float om = rm[j], os = rs[j];
        float nm = fmaxf(M, om);
        S = S * __expf(M - nm) + os * __expf(om - nm);
        M = nm;
    }
    float inv = __frcp_rn(S);

    for (int i = tid; i < N4; i += 256) {
        float4 v = p[i];
        v.x = __expf(v.x - M) * inv;
        v.y = __expf(v.y - M) * inv;
        v.z = __expf(v.z - M) * inv;
        v.w = __expf(v.w - M) * inv;
        p[i] = v;
    }
}

// ---------------------------------------------------------------------------

static inline int cdiv(int a, int b) { return (a + b - 1) / b; }

extern "C" void kernel_launch(void* const* d_in, const int* in_sizes, int n_in,
                              void* d_out, int out_size) {
    const float* X  = (const float*)d_in[0];  // [B,T,XD]
    const float* H  = (const float*)d_in[1];  // [B,T,HD]
    const float* W1 = (const float*)d_in[2];  // [XD,HD]
    const float* W2 = (const float*)d_in[3];  // [CN,T]
    float* out = (float*)d_out;               // [B,CN,HD]

    float *Z, *Y, *L;
    cudaGetSymbolAddress((void**)&Z, g_Z);
    cudaGetSymbolAddress((void**)&Y, g_Y);
    cudaGetSymbolAddress((void**)&L, g_L);

    const float scale = 1.0f / sqrtf((float)XD * (float)HD);

    constexpr int SMEM = 2 * 6912 * 4;   // 55296 B (2 stages of raw fp32)

    static bool attr_done = false;
    if (!attr_done) {
        cudaFuncSetAttribute(gemm_tf32<true, true>,
            cudaFuncAttributeMaxDynamicSharedMemorySize, SMEM);
        cudaFuncSetAttribute(gemm_tf32<false, true>,
            cudaFuncAttributeMaxDynamicSharedMemorySize, SMEM);
        cudaFuncSetAttribute(gemm_tf32<true, false>,
            cudaFuncAttributeMaxDynamicSharedMemorySize, SMEM);
        attr_done = true;
    }

    // 1) Z[b] = W2 @ X[b]          [CN,T] x [T,XD] -> [CN,XD]   (NN, 3xTF32)
    gemm_tf32<true, true><<<dim3(cdiv(CN,128), cdiv(XD,64), B_), 256, SMEM>>>(
        W2, 0, X, (size_t)T_ * XD, Z, (size_t)CN * XD, CN, XD, T_, 1.0f);

    // 2) Y[b] = Z[b] @ W1          [CN,XD] x [XD,HD] -> [CN,HD] (NN, 3xTF32)
    gemm_tf32<true, true><<<dim3(cdiv(CN,128), cdiv(HD,64), B_), 256, SMEM>>>(
        Z, (size_t)CN * XD, W1, 0, Y, (size_t)CN * HD, CN, HD, XD, 1.0f);

    // 3) L[b] = scale * Y[b] @ H[b]^T   [CN,HD] x [T,HD]^T -> [CN,T]  (NT, 3xTF32)
    gemm_tf32<false, true><<<dim3(cdiv(CN,128), cdiv(T_,64), B_), 256, SMEM>>>(
        Y, (size_t)CN * HD, H, (size_t)T_ * HD, L, (size_t)CN * T_, CN, T_, HD, scale);

    // 4) softmax rows of L
    softmax_rows<<<dim3(CN, B_), 256>>>();

    // 5) out[b] = P[b] @ H[b]      [CN,T] x [T,HD] -> [CN,HD]  (NN, single tf32)
    gemm_tf32<true, false><<<dim3(cdiv(CN,128), cdiv(HD,64), B_), 256, SMEM>>>(
        L, (size_t)CN * T_, H, (size_t)T_ * HD, out, (size_t)CN * HD, CN, HD, T_, 1.0f);
}

// round 7
// speedup vs baseline: 2.3568x; 1.2041x over previous
#include <cuda_runtime.h>
#include <cuda_bf16.h>
#include <math_constants.h>
#include <cstdint>

#define B_  64
#define T_  1380
#define TP  1408        // T padded to multiple of 32
#define TP2 (TP/2)      // 704 packed pairs
#define T2  (T_/2)      // 690 real pairs
#define XD  96
#define XP2 (XD/2)      // 48
#define HD  192
#define HP2 (HD/2)      // 96
#define CN  345

// ---------------------------------------------------------------------------
// Scratch (device globals). hi/lo bf16 pairs packed in uint32 (low half = lower k).
// ---------------------------------------------------------------------------
__device__ uint32_t g_W2h[(size_t)CN * TP2],      g_W2l[(size_t)CN * TP2];
__device__ uint32_t g_Xth[(size_t)B_ * XD * TP2], g_Xtl[(size_t)B_ * XD * TP2];
__device__ uint32_t g_W1th[(size_t)HD * XP2],     g_W1tl[(size_t)HD * XP2];
__device__ uint32_t g_Hh [(size_t)B_ * T_ * HP2], g_Hl [(size_t)B_ * T_ * HP2];
__device__ uint32_t g_Hth[(size_t)B_ * HD * TP2], g_Htl[(size_t)B_ * HD * TP2];
__device__ uint32_t g_Zh [(size_t)B_ * CN * XP2], g_Zl [(size_t)B_ * CN * XP2];
__device__ uint32_t g_Yh [(size_t)B_ * CN * HP2], g_Yl [(size_t)B_ * CN * HP2];
__device__ uint32_t g_Ph [(size_t)B_ * CN * TP2], g_Pl [(size_t)B_ * CN * TP2];
__device__ float    g_L  [(size_t)B_ * CN * T_];

// ---------------------------------------------------------------------------
// Helpers
// ---------------------------------------------------------------------------
__device__ __forceinline__ void split_pair(float x0, float x1,
                                           uint32_t& hi, uint32_t& lo) {
    __nv_bfloat16 h0 = __float2bfloat16_rn(x0);
    __nv_bfloat16 h1 = __float2bfloat16_rn(x1);
    float r0 = x0 - __bfloat162float(h0);
    float r1 = x1 - __bfloat162float(h1);
    __nv_bfloat16 l0 = __float2bfloat16_rn(r0);
    __nv_bfloat16 l1 = __float2bfloat16_rn(r1);
    hi = ((uint32_t)__bfloat16_as_ushort(h1) << 16) | __bfloat16_as_ushort(h0);
    lo = ((uint32_t)__bfloat16_as_ushort(l1) << 16) | __bfloat16_as_ushort(l0);
}

__device__ __forceinline__ void mma_bf16(float* c, const uint32_t* a, const uint32_t* b) {
    asm volatile(
        "mma.sync.aligned.m16n8k16.row.col.f32.bf16.bf16.f32 "
        "{%0,%1,%2,%3}, {%4,%5,%6,%7}, {%8,%9}, {%0,%1,%2,%3};"
        : "+f"(c[0]), "+f"(c[1]), "+f"(c[2]), "+f"(c[3])
        : "r"(a[0]), "r"(a[1]), "r"(a[2]), "r"(a[3]),
          "r"(b[0]), "r"(b[1]));
}

// 16B cp.async with zero-fill when !ok (src must be a valid address)
__device__ __forceinline__ void cp16(uint32_t dst, const void* src, bool ok) {
    asm volatile(
        "{\n\t.reg .pred p;\n\t.reg .b32 sz;\n\t"
        "setp.ne.u32 p, %2, 0;\n\t"
        "selp.b32 sz, 16, 0, p;\n\t"
        "cp.async.cg.shared.global [%0], [%1], 16, sz;\n\t}"
        :: "r"(dst), "l"(src), "r"((uint32_t)ok) : "memory");
}
#define CP_COMMIT() asm volatile("cp.async.commit_group;" ::: "memory")

// ---------------------------------------------------------------------------
// Prepass 1: elementwise split+pack (no transpose), pad columns with zeros.
// src fp32 [rows][C] -> dh/dl u32 [rows][Cp2]. C even.
// ---------------------------------------------------------------------------
__global__ void split_pack(const float* __restrict__ src,
                           uint32_t* __restrict__ dh, uint32_t* __restrict__ dl,
                           int rows, int C, int Cp2) {
    size_t idx = (size_t)blockIdx.x * 256 + threadIdx.x;
    size_t total = (size_t)rows * Cp2;
    if (idx >= total) return;
    int r = (int)(idx / Cp2);
    int j = (int)(idx - (size_t)r * Cp2);
    float2 v = make_float2(0.f, 0.f);
    if (2 * j < C)
        v = *reinterpret_cast<const float2*>(src + (size_t)r * C + 2 * j);
    uint32_t hi, lo;
    split_pair(v.x, v.y, hi, lo);
    dh[idx] = hi;
    dl[idx] = lo;
}

// ---------------------------------------------------------------------------
// Prepass 2: split + transpose + pack.
// src fp32 [b][R][C] -> dh/dl u32 [b][C][Rp2] (pairs along R, zero-padded).
// Grid: (Rp/32, ceil(C/32), batches), block (32,8).
// ---------------------------------------------------------------------------
__global__ void split_transpose(const float* __restrict__ src, size_t sSrc,
                                uint32_t* __restrict__ dh, uint32_t* __restrict__ dl,
                                size_t sDst, int R, int C, int Rp2) {
    __shared__ float t[32][33];
    const int b = blockIdx.z;
    src += sSrc * b;
    dh  += sDst * b;
    dl  += sDst * b;
    const int r0 = blockIdx.x * 32;
    const int c0 = blockIdx.y * 32;
    const int tx = threadIdx.x, ty = threadIdx.y;

    #pragma unroll
    for (int i = 0; i < 4; i++) {
        int r = r0 + ty + i * 8, c = c0 + tx;
        t[ty + i * 8][tx] = (r < R && c < C) ? src[(size_t)r * C + c] : 0.f;
    }
    __syncthreads();
    if (tx < 16) {
        #pragma unroll
        for (int i = 0; i < 4; i++) {
            int cc = ty + i * 8, c = c0 + cc;
            if (c < C) {
                uint32_t hi, lo;
                split_pair(t[2 * tx][cc], t[2 * tx + 1][cc], hi, lo);
                size_t o = (size_t)c * Rp2 + (r0 >> 1) + tx;
                dh[o] = hi;
                dl[o] = lo;
            }
        }
    }
}

// ---------------------------------------------------------------------------
// bf16 split-compensated tensor-core GEMM (all NT, packed operands).
//   C[b] = alpha * A[b] (M x Kp) @ B[b] (N x Kp)^T,   3 products: hh+hl+lh
// A/B given as hi/lo packed-pair arrays [rows][Kp/2]. Kp % 32 == 0.
// BM=128, BN=64, BK=32, 256 thr (8 warps 4x2), warp tile 32x32, m16n8k16.
// cp.async double-buffered. smem pitch 20 u32 (conflict-free: 20*l4+lk).
// OSPLIT: write Ch/Cl packed split (for Z,Y); else Cf fp32.
// ---------------------------------------------------------------------------
template<bool OSPLIT>
__global__ __launch_bounds__(256)
void gemm_bf16s(const uint32_t* __restrict__ Ah, const uint32_t* __restrict__ Al, size_t sA,
                const uint32_t* __restrict__ Bh, const uint32_t* __restrict__ Bl, size_t sB,
                float* __restrict__ Cf, uint32_t* __restrict__ Ch, uint32_t* __restrict__ Cl,
                size_t sC, int M, int N, int Kp, float alpha)
{
    constexpr int PITCH = 20;
    constexpr int OFF_AL = 2560, OFF_BH = 5120, OFF_BL = 6400;
    constexpr int STG = 7680;   // u32 per stage

    extern __shared__ uint32_t sm[];

    const int b = blockIdx.z;
    Ah += sA * b;  Al += sA * b;
    Bh += sB * b;  Bl += sB * b;
    const int m0 = blockIdx.x * 128;
    const int n0 = blockIdx.y * 64;
    const int tid  = threadIdx.x;
    const int warp = tid >> 5, lane = tid & 31;
    const int wm = warp >> 1, wn = warp & 1;
    const int l4 = lane >> 2, lk = lane & 3;
    const int Kp2 = Kp >> 1;

    float acc[2][4][4] = {};
    const int nck = Kp >> 5;

    auto load_tile = [&](int ck, int st) {
        uint32_t* dst = sm + st * STG;
        const int k0 = ck * 16;   // u32 (pair) offset
        #pragma unroll
        for (int i = 0; i < 4; i++) {            // A: 1024 chunks (hi then lo)
            int idx = tid + i * 256;
            int arr = idx >> 9, rem = idx & 511;
            int r = rem >> 2, c4 = rem & 3;
            int gm = m0 + r;
            bool ok = gm < M;
            const uint32_t* base = arr ? Al : Ah;
            const uint32_t* src = ok ? (base + (size_t)gm * Kp2 + k0 + c4 * 4) : base;
            cp16((uint32_t)__cvta_generic_to_shared(dst + arr * OFF_AL + r * PITCH + c4 * 4),
                 src, ok);
        }
        #pragma unroll
        for (int i = 0; i < 2; i++) {            // B: 512 chunks
            int idx = tid + i * 256;
            int arr = idx >> 8, rem = idx & 255;
            int r = rem >> 2, c4 = rem & 3;
            int gn = n0 + r;
            bool ok = gn < N;
            const uint32_t* base = arr ? Bl : Bh;
            const uint32_t* src = ok ? (base + (size_t)gn * Kp2 + k0 + c4 * 4) : base;
            cp16((uint32_t)__cvta_generic_to_shared(dst + OFF_BH + arr * 1280 + r * PITCH + c4 * 4),
                 src, ok);
        }
    };

    load_tile(0, 0);
    CP_COMMIT();

    for (int ck = 0; ck < nck; ck++) {
        if (ck + 1 < nck) {
            load_tile(ck + 1, (ck + 1) & 1);
            CP_COMMIT();
            asm volatile("cp.async.wait_group 1;" ::: "memory");
        } else {
            asm volatile("cp.async.wait_group 0;" ::: "memory");
        }
        __syncthreads();

        const uint32_t* pA = sm + (ck & 1) * STG;
        const uint32_t* pB = pA + OFF_BH;

        #pragma unroll
        for (int kk = 0; kk < 2; kk++) {
            const int ko = kk * 8;
            uint32_t a_h[2][4], a_l[2][4], b_h[4][2], b_l[4][2];
            #pragma unroll
            for (int mi = 0; mi < 2; mi++) {
                int rb = wm * 32 + mi * 16 + l4;
                a_h[mi][0] = pA[rb * PITCH + ko + lk];
                a_h[mi][1] = pA[(rb + 8) * PITCH + ko + lk];
                a_h[mi][2] = pA[rb * PITCH + ko + lk + 4];
                a_h[mi][3] = pA[(rb + 8) * PITCH + ko + lk + 4];
                a_l[mi][0] = pA[OFF_AL + rb * PITCH + ko + lk];
                a_l[mi][1] = pA[OFF_AL + (rb + 8) * PITCH + ko + lk];
                a_l[mi][2] = pA[OFF_AL + rb * PITCH + ko + lk + 4];
                a_l[mi][3] = pA[OFF_AL + (rb + 8) * PITCH + ko + lk + 4];
            }
            #pragma unroll
            for (int ni = 0; ni < 4; ni++) {
                int nb = wn * 32 + ni * 8 + l4;
                b_h[ni][0] = pB[nb * PITCH + ko + lk];
                b_h[ni][1] = pB[nb * PITCH + ko + lk + 4];
                b_l[ni][0] = pB[1280 + nb * PITCH + ko + lk];
                b_l[ni][1] = pB[1280 + nb * PITCH + ko + lk + 4];
            }
            #pragma unroll
            for (int mi = 0; mi < 2; mi++)
                #pragma unroll
                for (int ni = 0; ni < 4; ni++) {
                    mma_bf16(acc[mi][ni], a_h[mi], b_h[ni]);
                    mma_bf16(acc[mi][ni], a_h[mi], b_l[ni]);
                    mma_bf16(acc[mi][ni], a_l[mi], b_h[ni]);
                }
        }
        __syncthreads();
    }

    // ---- epilogue ----
    const int N2 = N >> 1;
    #pragma unroll
    for (int mi = 0; mi < 2; mi++) {
        #pragma unroll
        for (int ni = 0; ni < 4; ni++) {
            int r0 = m0 + wm * 32 + mi * 16 + l4;
            int c0 = n0 + wn * 32 + ni * 8 + 2 * lk;
            if (c0 < N) {
                if (OSPLIT) {
                    int pj = c0 >> 1;
                    if (r0 < M) {
                        uint32_t hi, lo;
                        split_pair(alpha * acc[mi][ni][0], alpha * acc[mi][ni][1], hi, lo);
                        Ch[sC * b + (size_t)r0 * N2 + pj] = hi;
                        Cl[sC * b + (size_t)r0 * N2 + pj] = lo;
                    }
                    if (r0 + 8 < M) {
                        uint32_t hi, lo;
                        split_pair(alpha * acc[mi][ni][2], alpha * acc[mi][ni][3], hi, lo);
                        Ch[sC * b + (size_t)(r0 + 8) * N2 + pj] = hi;
                        Cl[sC * b + (size_t)(r0 + 8) * N2 + pj] = lo;
                    }
                } else {
                    if (r0 < M) {
                        float2 v = make_float2(alpha * acc[mi][ni][0], alpha * acc[mi][ni][1]);
                        *reinterpret_cast<float2*>(Cf + sC * b + (size_t)r0 * N + c0) = v;
                    }
                    if (r0 + 8 < M) {
                        float2 v = make_float2(alpha * acc[mi][ni][2], alpha * acc[mi][ni][3]);
                        *reinterpret_cast<float2*>(Cf + sC * b + (size_t)(r0 + 8) * N + c0) = v;
                    }
                }
            }
        }
    }
}

// ---------------------------------------------------------------------------
// Softmax rows of g_L; writes split-packed probs to g_Ph/g_Pl (zero-padded).
// 3 passes over the row (max / sum / write), one block per row.
// ---------------------------------------------------------------------------
__global__ void softmax_split() {
    const size_t row = (size_t)blockIdx.y * CN + blockIdx.x;
    const float* Lr = g_L + row * T_;
    const float4* p4 = reinterpret_cast<const float4*>(Lr);
    constexpr int N4 = T_ / 4;   // 345
    const int tid = threadIdx.x;
    const int lane = tid & 31, warp = tid >> 5;
    __shared__ float red[8];

    // 1) max
    float m = -CUDART_INF_F;
    for (int i = tid; i < N4; i += 256) {
        float4 v = p4[i];
        m = fmaxf(m, fmaxf(fmaxf(v.x, v.y), fmaxf(v.z, v.w)));
    }
    #pragma unroll
    for (int o = 16; o > 0; o >>= 1) m = fmaxf(m, __shfl_xor_sync(0xffffffffu, m, o));
    if (lane == 0) red[warp] = m;
    __syncthreads();
    float M = red[0];
    #pragma unroll
    for (int j = 1; j < 8; j++) M = fmaxf(M, red[j]);
    __syncthreads();

    // 2) sum of exp (no store)
    float s = 0.f;
    for (int i = tid; i < N4; i += 256) {
        float4 v = p4[i];
        s += __expf(v.x - M) + __expf(v.y - M) + __expf(v.z - M) + __expf(v.w - M);
    }
    #pragma unroll
    for (int o = 16; o > 0; o >>= 1) s += __shfl_xor_sync(0xffffffffu, s, o);
    if (lane == 0) red[warp] = s;
    __syncthreads();
    float S = red[0];
    #pragma unroll
    for (int j = 1; j < 8; j++) S += red[j];
    float inv = __frcp_rn(S);

    // 3) write split-packed probabilities
    uint32_t* Ph = g_Ph + row * TP2;
    uint32_t* Pl = g_Pl + row * TP2;
    const float2* p2 = reinterpret_cast<const float2*>(Lr);
    for (int j = tid; j < TP2; j += 256) {
        uint32_t hi = 0, lo = 0;
        if (j < T2) {
            float2 v = p2[j];
            split_pair(__expf(v.x - M) * inv, __expf(v.y - M) * inv, hi, lo);
        }
        Ph[j] = hi;
        Pl[j] = lo;
    }
}

// ---------------------------------------------------------------------------

static inline int cdiv(int a, int b) { return (a + b - 1) / b; }

extern "C" void kernel_launch(void* const* d_in, const int* in_sizes, int n_in,
                              void* d_out, int out_size) {
    const float* X  = (const float*)d_in[0];  // [B,T,XD]
    const float* H  = (const float*)d_in[1];  // [B,T,HD]
    const float* W1 = (const float*)d_in[2];  // [XD,HD]
    const float* W2 = (const float*)d_in[3];  // [CN,T]
    float* out = (float*)d_out;               // [B,CN,HD]

    uint32_t *W2h, *W2l, *Xth, *Xtl, *W1th, *W1tl, *Hh, *Hl, *Hth, *Htl;
    uint32_t *Zh, *Zl, *Yh, *Yl, *Ph, *Pl;
    float* L;
    cudaGetSymbolAddress((void**)&W2h, g_W2h);  cudaGetSymbolAddress((void**)&W2l, g_W2l);
    cudaGetSymbolAddress((void**)&Xth, g_Xth);  cudaGetSymbolAddress((void**)&Xtl, g_Xtl);
    cudaGetSymbolAddress((void**)&W1th, g_W1th); cudaGetSymbolAddress((void**)&W1tl, g_W1tl);
    cudaGetSymbolAddress((void**)&Hh, g_Hh);    cudaGetSymbolAddress((void**)&Hl, g_Hl);
    cudaGetSymbolAddress((void**)&Hth, g_Hth);  cudaGetSymbolAddress((void**)&Htl, g_Htl);
    cudaGetSymbolAddress((void**)&Zh, g_Zh);    cudaGetSymbolAddress((void**)&Zl, g_Zl);
    cudaGetSymbolAddress((void**)&Yh, g_Yh);    cudaGetSymbolAddress((void**)&Yl, g_Yl);
    cudaGetSymbolAddress((void**)&Ph, g_Ph);    cudaGetSymbolAddress((void**)&Pl, g_Pl);
    cudaGetSymbolAddress((void**)&L,  g_L);

    const float scale = 1.0f / sqrtf((float)XD * (float)HD);

    constexpr int SMEM = 2 * 7680 * 4;   // 61440 B

    static bool attr_done = false;
    if (!attr_done) {
        cudaFuncSetAttribute(gemm_bf16s<true>,
            cudaFuncAttributeMaxDynamicSharedMemorySize, SMEM);
        cudaFuncSetAttribute(gemm_bf16s<false>,
            cudaFuncAttributeMaxDynamicSharedMemorySize, SMEM);
        attr_done = true;
    }

    // ---- prepass: split everything into bf16 hi/lo (+ transposes, k-major) ----
    {
        size_t tot = (size_t)CN * TP2;                     // W2 [CN,T] -> [CN,TP2]
        split_pack<<<(int)cdiv((int)tot, 256), 256>>>(W2, W2h, W2l, CN, T_, TP2);
    }
    {
        size_t tot = (size_t)B_ * T_ * HP2;                // H [B*T,HD] -> [B*T,HP2]
        split_pack<<<(int)((tot + 255) / 256), 256>>>(H, Hh, Hl, B_ * T_, HD, HP2);
    }
    split_transpose<<<dim3(TP / 32, cdiv(XD, 32), B_), dim3(32, 8)>>>(
        X, (size_t)T_ * XD, Xth, Xtl, (size_t)XD * TP2, T_, XD, TP2);
    split_transpose<<<dim3(TP / 32, cdiv(HD, 32), B_), dim3(32, 8)>>>(
        H, (size_t)T_ * HD, Hth, Htl, (size_t)HD * TP2, T_, HD, TP2);
    split_transpose<<<dim3(XD / 32, cdiv(HD, 32), 1), dim3(32, 8)>>>(
        W1, 0, W1th, W1tl, 0, XD, HD, XP2);

    // 1) Z[b] = W2 @ X[b]^T^T   A=W2 [CN,TP], B=Xt [XD,TP]  -> Z split [CN,XP2]
    gemm_bf16s<true><<<dim3(cdiv(CN, 128), cdiv(XD, 64), B_), 256, SMEM>>>(
        W2h, W2l, 0, Xth, Xtl, (size_t)XD * TP2,
        nullptr, Zh, Zl, (size_t)CN * XP2, CN, XD, TP, 1.0f);

    // 2) Y[b] = Z[b] @ W1       A=Z [CN,XD], B=W1t [HD,XD]  -> Y split [CN,HP2]
    gemm_bf16s<true><<<dim3(cdiv(CN, 128), cdiv(HD, 64), B_), 256, SMEM>>>(
        Zh, Zl, (size_t)CN * XP2, W1th, W1tl, 0,
        nullptr, Yh, Yl, (size_t)CN * HP2, CN, HD, XD, 1.0f);

    // 3) L[b] = scale * Y[b] @ H[b]^T   A=Y [CN,HD], B=H [T,HD] -> L fp32
    gemm_bf16s<false><<<dim3(cdiv(CN, 128), cdiv(T_, 64), B_), 256, SMEM>>>(
        Yh, Yl, (size_t)CN * HP2, Hh, Hl, (size_t)T_ * HP2,
        L, nullptr, nullptr, (size_t)CN * T_, CN, T_, HD, scale);

    // 4) softmax rows of L -> P split [CN,TP2]
    softmax_split<<<dim3(CN, B_), 256>>>();

    // 5) out[b] = P[b] @ H[b]   A=P [CN,TP], B=Ht [HD,TP] -> out fp32
    gemm_bf16s<false><<<dim3(cdiv(CN, 128), cdiv(HD, 64), B_), 256, SMEM>>>(
        Ph, Pl, (size_t)CN * TP2, Hth, Htl, (size_t)HD * TP2,
        out, nullptr, nullptr, (size_t)CN * HD, CN, HD, TP, 1.0f);
}